// round 3
// baseline (speedup 1.0000x reference)
#include <cuda_runtime.h>
#include <math.h>

// NTXentLoss: B=2048, P=16, N=128, D=512 (fp32).
// HBM-bound streaming: ~520MB mandatory traffic (negatives dominate).
// One block per anchor b; warp-per-negative dot products; masked LSE.
// R2 fix: neg_mask is int32 (bool promoted by harness), not uint8.

#define DDIM 512
#define D4 (DDIM / 4)        // 128 float4 per row
#define THREADS 256
#define NWARPS (THREADS / 32)
#define TEMP_INV 10.0f
#define COS_EPS 1e-8f

// scratch for per-anchor losses (no cudaMalloc allowed)
__device__ float g_loss[4096];

__device__ __forceinline__ float warpReduceSum(float v) {
#pragma unroll
    for (int o = 16; o; o >>= 1) v += __shfl_down_sync(0xffffffffu, v, o);
    return v;
}

__device__ __forceinline__ float warpReduceMax(float v) {
#pragma unroll
    for (int o = 16; o; o >>= 1) v = fmaxf(v, __shfl_down_sync(0xffffffffu, v, o));
    return v;
}

// Result valid in thread 0 only. Caller must __syncthreads() between uses of sbuf.
__device__ __forceinline__ float blockReduceSum(float v, float* sbuf) {
    int lane = threadIdx.x & 31, wid = threadIdx.x >> 5;
    v = warpReduceSum(v);
    if (lane == 0) sbuf[wid] = v;
    __syncthreads();
    v = (threadIdx.x < NWARPS) ? sbuf[threadIdx.x] : 0.0f;
    if (wid == 0) {
#pragma unroll
        for (int o = NWARPS / 2; o; o >>= 1) v += __shfl_down_sync(0xffffffffu, v, o);
    }
    return v;
}

__device__ __forceinline__ float blockReduceMax(float v, float* sbuf) {
    int lane = threadIdx.x & 31, wid = threadIdx.x >> 5;
    v = warpReduceMax(v);
    if (lane == 0) sbuf[wid] = v;
    __syncthreads();
    v = (threadIdx.x < NWARPS) ? sbuf[threadIdx.x] : -INFINITY;
    if (wid == 0) {
#pragma unroll
        for (int o = NWARPS / 2; o; o >>= 1) v = fmaxf(v, __shfl_down_sync(0xffffffffu, v, o));
    }
    return v;
}

__global__ void __launch_bounds__(THREADS)
ntxent_main_kernel(const float* __restrict__ target,
                   const float* __restrict__ positives,
                   const float* __restrict__ negatives,
                   const int* __restrict__ pos_idx,
                   const int* __restrict__ neg_mask,
                   int P, int N) {
    const int b = blockIdx.x;
    const int tid = threadIdx.x;
    const int lane = tid & 31;
    const int w = tid >> 5;

    __shared__ float4 s_tgt[D4];     // 2KB target row
    __shared__ float s_sims[256];    // per-negative sims (N <= 256)
    __shared__ float s_red[NWARPS];
    __shared__ float s_bcast[4];     // [0]=||t||, [1]=pos_sim, [2]=lse max

    // --- load target row, compute ||t||^2 ---
    float tq = 0.0f;
    if (tid < D4) {
        float4 t = ((const float4*)(target + (size_t)b * DDIM))[tid];
        s_tgt[tid] = t;
        tq = t.x * t.x + t.y * t.y + t.z * t.z + t.w * t.w;
    }
    __syncthreads();
    float tsum = blockReduceSum(tq, s_red);
    if (tid == 0) s_bcast[0] = sqrtf(tsum);
    __syncthreads();

    // --- gathered positive: dot + norm ---
    const int pi = pos_idx[b];
    const float4* pos4 = (const float4*)(positives + ((size_t)b * P + pi) * (size_t)DDIM);
    float pdot = 0.0f, pq = 0.0f;
    if (tid < D4) {
        float4 p = pos4[tid];
        float4 t = s_tgt[tid];
        pdot = fmaf(p.x, t.x, fmaf(p.y, t.y, fmaf(p.z, t.z, p.w * t.w)));
        pq = fmaf(p.x, p.x, fmaf(p.y, p.y, fmaf(p.z, p.z, p.w * p.w)));
    }
    float pd = blockReduceSum(pdot, s_red);
    __syncthreads();
    float pn = blockReduceSum(pq, s_red);
    if (tid == 0) {
        float denom = fmaxf(sqrtf(pn) * s_bcast[0], COS_EPS);
        s_bcast[1] = (pd / denom) * TEMP_INV;
    }
    __syncthreads();
    const float tnorm = s_bcast[0];
    const float pos_sim = s_bcast[1];

    // --- negatives: warp-per-row dot + norm (coalesced float4) ---
    const float4* negb = (const float4*)(negatives + (size_t)b * (size_t)N * DDIM);
    for (int n = w; n < N; n += NWARPS) {
        const float4* v = negb + (size_t)n * D4;
        float dot = 0.0f, q = 0.0f;
#pragma unroll
        for (int i = 0; i < D4 / 32; i++) {   // 4 iters
            float4 x = v[lane + 32 * i];
            float4 t = s_tgt[lane + 32 * i];
            dot = fmaf(x.x, t.x, dot);
            dot = fmaf(x.y, t.y, dot);
            dot = fmaf(x.z, t.z, dot);
            dot = fmaf(x.w, t.w, dot);
            q = fmaf(x.x, x.x, q);
            q = fmaf(x.y, x.y, q);
            q = fmaf(x.z, x.z, q);
            q = fmaf(x.w, x.w, q);
        }
        dot = warpReduceSum(dot);
        q = warpReduceSum(q);
        if (lane == 0) {
            float denom = fmaxf(sqrtf(q) * tnorm, COS_EPS);
            s_sims[n] = (dot / denom) * TEMP_INV;
        }
    }
    __syncthreads();

    // --- masked logsumexp over [pos_sim, neg sims] ---
    float x = -INFINITY;
    if (tid < N) {
        x = (neg_mask[(size_t)b * N + tid] != 0) ? s_sims[tid] : -INFINITY;
    } else if (tid == N) {
        x = pos_sim;
    }
    float m = blockReduceMax(x, s_red);
    if (tid == 0) s_bcast[2] = m;
    __syncthreads();
    m = s_bcast[2];
    float e = (x == -INFINITY) ? 0.0f : expf(x - m);
    __syncthreads();  // protect s_red reuse
    float S = blockReduceSum(e, s_red);
    if (tid == 0) {
        g_loss[b] = logf(S) + m - pos_sim;
    }
}

__global__ void __launch_bounds__(THREADS)
ntxent_reduce_kernel(float* __restrict__ out, int B) {
    __shared__ float s_red[NWARPS];
    float v = 0.0f;
    for (int i = threadIdx.x; i < B; i += THREADS) v += g_loss[i];
    v = blockReduceSum(v, s_red);
    if (threadIdx.x == 0) out[0] = v / (float)B;
}

extern "C" void kernel_launch(void* const* d_in, const int* in_sizes, int n_in,
                              void* d_out, int out_size) {
    const float* target = (const float*)d_in[0];
    const float* positives = (const float*)d_in[1];
    const float* negatives = (const float*)d_in[2];
    const int* pos_idx = (const int*)d_in[3];
    const int* neg_mask = (const int*)d_in[4];
    float* out = (float*)d_out;

    const int B = in_sizes[0] / DDIM;                 // 2048
    const int P = in_sizes[1] / in_sizes[0];          // 16
    const int N = in_sizes[2] / in_sizes[0];          // 128

    ntxent_main_kernel<<<B, THREADS>>>(target, positives, negatives, pos_idx,
                                       neg_mask, P, N);
    ntxent_reduce_kernel<<<1, THREADS>>>(out, B);
}

// round 4
// speedup vs baseline: 1.5021x; 1.5021x over previous
#include <cuda_runtime.h>
#include <math.h>

// NTXentLoss: B=2048, P=16, N=128, D=512 (fp32).
// R4: skip masked-out negatives entirely (mask has weight 0 in the LSE) ->
//     ~50% of the 512MB negative traffic eliminated. Fuse mean-reduction
//     into the main kernel via deterministic last-block pattern.

#define DDIM 512
#define D4 (DDIM / 4)        // 128 float4 per row
#define THREADS 256
#define NWARPS (THREADS / 32)
#define TEMP_INV 10.0f
#define COS_EPS 1e-8f

// scratch (no cudaMalloc allowed)
__device__ float g_loss[4096];
__device__ unsigned int g_count = 0;

__device__ __forceinline__ float warpReduceSum(float v) {
#pragma unroll
    for (int o = 16; o; o >>= 1) v += __shfl_down_sync(0xffffffffu, v, o);
    return v;
}

__device__ __forceinline__ float warpReduceMax(float v) {
#pragma unroll
    for (int o = 16; o; o >>= 1) v = fmaxf(v, __shfl_down_sync(0xffffffffu, v, o));
    return v;
}

// Result valid in thread 0 only. Caller must __syncthreads() between reuses of sbuf.
__device__ __forceinline__ float blockReduceSum(float v, float* sbuf) {
    int lane = threadIdx.x & 31, wid = threadIdx.x >> 5;
    v = warpReduceSum(v);
    if (lane == 0) sbuf[wid] = v;
    __syncthreads();
    v = (threadIdx.x < NWARPS) ? sbuf[threadIdx.x] : 0.0f;
    if (wid == 0) {
#pragma unroll
        for (int o = NWARPS / 2; o; o >>= 1) v += __shfl_down_sync(0xffffffffu, v, o);
    }
    return v;
}

__device__ __forceinline__ float blockReduceMax(float v, float* sbuf) {
    int lane = threadIdx.x & 31, wid = threadIdx.x >> 5;
    v = warpReduceMax(v);
    if (lane == 0) sbuf[wid] = v;
    __syncthreads();
    v = (threadIdx.x < NWARPS) ? sbuf[threadIdx.x] : -INFINITY;
    if (wid == 0) {
#pragma unroll
        for (int o = NWARPS / 2; o; o >>= 1) v = fmaxf(v, __shfl_down_sync(0xffffffffu, v, o));
    }
    return v;
}

__global__ void __launch_bounds__(THREADS)
ntxent_main_kernel(const float* __restrict__ target,
                   const float* __restrict__ positives,
                   const float* __restrict__ negatives,
                   const int* __restrict__ pos_idx,
                   const int* __restrict__ neg_mask,
                   float* __restrict__ out,
                   int B, int P, int N) {
    const int b = blockIdx.x;
    const int tid = threadIdx.x;
    const int lane = tid & 31;
    const int w = tid >> 5;

    __shared__ float4 s_tgt[D4];      // 2KB target row
    __shared__ float s_sims[256];     // sims of VALID negatives, compacted
    __shared__ int   s_valid[256];    // compacted valid negative indices
    __shared__ int   s_wcnt[NWARPS];  // per-warp valid counts
    __shared__ float s_red[NWARPS];
    __shared__ float s_bcast[4];      // [0]=||t||, [1]=pos_sim, [2]=lse max
    __shared__ int   s_islast;

    // --- compact valid negative indices (deterministic prefix via ballot) ---
    int mvalid = 0;
    if (tid < N) mvalid = (neg_mask[(size_t)b * N + tid] != 0);
    unsigned bal = __ballot_sync(0xffffffffu, mvalid);
    if (lane == 0) s_wcnt[w] = __popc(bal);

    // --- load target row, compute ||t||^2 ---
    float tq = 0.0f;
    if (tid < D4) {
        float4 t = ((const float4*)(target + (size_t)b * DDIM))[tid];
        s_tgt[tid] = t;
        tq = t.x * t.x + t.y * t.y + t.z * t.z + t.w * t.w;
    }
    __syncthreads();

    int off = 0, M = 0;
#pragma unroll
    for (int j = 0; j < NWARPS; j++) {
        int c = s_wcnt[j];
        if (j < w) off += c;
        M += c;
    }
    if (mvalid) s_valid[off + __popc(bal & ((1u << lane) - 1u))] = tid;

    float tsum = blockReduceSum(tq, s_red);
    if (tid == 0) s_bcast[0] = sqrtf(tsum);
    __syncthreads();

    // --- gathered positive: dot + norm ---
    const int pi = pos_idx[b];
    const float4* pos4 = (const float4*)(positives + ((size_t)b * P + pi) * (size_t)DDIM);
    float pdot = 0.0f, pq = 0.0f;
    if (tid < D4) {
        float4 p = pos4[tid];
        float4 t = s_tgt[tid];
        pdot = fmaf(p.x, t.x, fmaf(p.y, t.y, fmaf(p.z, t.z, p.w * t.w)));
        pq   = fmaf(p.x, p.x, fmaf(p.y, p.y, fmaf(p.z, p.z, p.w * p.w)));
    }
    float pd = blockReduceSum(pdot, s_red);
    __syncthreads();
    float pn = blockReduceSum(pq, s_red);
    if (tid == 0) {
        float denom = fmaxf(sqrtf(pn) * s_bcast[0], COS_EPS);
        s_bcast[1] = (pd / denom) * TEMP_INV;
    }
    __syncthreads();
    const float tnorm = s_bcast[0];
    const float pos_sim = s_bcast[1];

    // --- valid negatives only: warp-per-row dot + norm (coalesced float4) ---
    const float4* negb = (const float4*)(negatives + (size_t)b * (size_t)N * DDIM);
    for (int i = w; i < M; i += NWARPS) {
        const float4* v = negb + (size_t)s_valid[i] * D4;
        float dot = 0.0f, q = 0.0f;
#pragma unroll
        for (int k = 0; k < D4 / 32; k++) {   // 4 iters, loads front-batched
            float4 x = v[lane + 32 * k];
            float4 t = s_tgt[lane + 32 * k];
            dot = fmaf(x.x, t.x, dot);
            dot = fmaf(x.y, t.y, dot);
            dot = fmaf(x.z, t.z, dot);
            dot = fmaf(x.w, t.w, dot);
            q = fmaf(x.x, x.x, q);
            q = fmaf(x.y, x.y, q);
            q = fmaf(x.z, x.z, q);
            q = fmaf(x.w, x.w, q);
        }
        dot = warpReduceSum(dot);
        q = warpReduceSum(q);
        if (lane == 0) {
            float denom = fmaxf(sqrtf(q) * tnorm, COS_EPS);
            s_sims[i] = (dot / denom) * TEMP_INV;
        }
    }
    __syncthreads();

    // --- logsumexp over [pos_sim, valid neg sims] ---
    float x = -INFINITY;
    if (tid < M) x = s_sims[tid];
    else if (tid == M) x = pos_sim;
    float m = blockReduceMax(x, s_red);
    if (tid == 0) s_bcast[2] = m;
    __syncthreads();
    m = s_bcast[2];
    float e = (x == -INFINITY) ? 0.0f : expf(x - m);
    __syncthreads();  // protect s_red reuse
    float S = blockReduceSum(e, s_red);

    // --- publish per-anchor loss; last block reduces the mean ---
    if (tid == 0) {
        g_loss[b] = logf(S) + m - pos_sim;
        __threadfence();
        unsigned int old = atomicAdd(&g_count, 1u);
        s_islast = (old == (unsigned int)(B - 1));
    }
    __syncthreads();
    if (s_islast) {
        __threadfence();
        float v = 0.0f;
        for (int i = tid; i < B; i += THREADS) v += g_loss[i];
        __syncthreads();  // s_red safe to reuse
        v = blockReduceSum(v, s_red);
        if (tid == 0) {
            out[0] = v / (float)B;
            g_count = 0;  // reset for next graph replay
        }
    }
}

extern "C" void kernel_launch(void* const* d_in, const int* in_sizes, int n_in,
                              void* d_out, int out_size) {
    const float* target = (const float*)d_in[0];
    const float* positives = (const float*)d_in[1];
    const float* negatives = (const float*)d_in[2];
    const int* pos_idx = (const int*)d_in[3];
    const int* neg_mask = (const int*)d_in[4];
    float* out = (float*)d_out;

    const int B = in_sizes[0] / DDIM;                 // 2048
    const int P = in_sizes[1] / in_sizes[0];          // 16
    const int N = in_sizes[2] / in_sizes[0];          // 128

    ntxent_main_kernel<<<B, THREADS>>>(target, positives, negatives, pos_idx,
                                       neg_mask, out, B, P, N);
}

// round 5
// speedup vs baseline: 1.5400x; 1.0252x over previous
#include <cuda_runtime.h>
#include <math.h>

// NTXentLoss: B=2048, P=16, N=128, D=512 (fp32).
// R5: two negative rows per warp per iteration -> 8 front-batched LDG.128
//     (MLP 4->8) to cover DRAM latency (R4 was latency-bound: DRAM 59%,
//     issue 27%). Valid-only streaming + fused mean retained.

#define DDIM 512
#define D4 (DDIM / 4)        // 128 float4 per row
#define THREADS 256
#define NWARPS (THREADS / 32)
#define TEMP_INV 10.0f
#define COS_EPS 1e-8f

// scratch (no cudaMalloc allowed)
__device__ float g_loss[4096];
__device__ unsigned int g_count = 0;

__device__ __forceinline__ float warpReduceSum(float v) {
#pragma unroll
    for (int o = 16; o; o >>= 1) v += __shfl_down_sync(0xffffffffu, v, o);
    return v;
}

__device__ __forceinline__ float warpReduceMax(float v) {
#pragma unroll
    for (int o = 16; o; o >>= 1) v = fmaxf(v, __shfl_down_sync(0xffffffffu, v, o));
    return v;
}

// Result valid in thread 0 only. Caller must __syncthreads() between reuses of sbuf.
__device__ __forceinline__ float blockReduceSum(float v, float* sbuf) {
    int lane = threadIdx.x & 31, wid = threadIdx.x >> 5;
    v = warpReduceSum(v);
    if (lane == 0) sbuf[wid] = v;
    __syncthreads();
    v = (threadIdx.x < NWARPS) ? sbuf[threadIdx.x] : 0.0f;
    if (wid == 0) {
#pragma unroll
        for (int o = NWARPS / 2; o; o >>= 1) v += __shfl_down_sync(0xffffffffu, v, o);
    }
    return v;
}

__device__ __forceinline__ float blockReduceMax(float v, float* sbuf) {
    int lane = threadIdx.x & 31, wid = threadIdx.x >> 5;
    v = warpReduceMax(v);
    if (lane == 0) sbuf[wid] = v;
    __syncthreads();
    v = (threadIdx.x < NWARPS) ? sbuf[threadIdx.x] : -INFINITY;
    if (wid == 0) {
#pragma unroll
        for (int o = NWARPS / 2; o; o >>= 1) v = fmaxf(v, __shfl_down_sync(0xffffffffu, v, o));
    }
    return v;
}

__global__ void __launch_bounds__(THREADS)
ntxent_main_kernel(const float* __restrict__ target,
                   const float* __restrict__ positives,
                   const float* __restrict__ negatives,
                   const int* __restrict__ pos_idx,
                   const int* __restrict__ neg_mask,
                   float* __restrict__ out,
                   int B, int P, int N) {
    const int b = blockIdx.x;
    const int tid = threadIdx.x;
    const int lane = tid & 31;
    const int w = tid >> 5;

    __shared__ float4 s_tgt[D4];      // 2KB target row
    __shared__ float s_sims[256];     // sims of VALID negatives, compacted
    __shared__ int   s_valid[256];    // compacted valid negative indices
    __shared__ int   s_wcnt[NWARPS];  // per-warp valid counts
    __shared__ float s_red[NWARPS];
    __shared__ float s_bcast[4];      // [0]=||t||, [1]=pos_sim, [2]=lse max
    __shared__ int   s_islast;

    // --- compact valid negative indices (deterministic prefix via ballot) ---
    int mvalid = 0;
    if (tid < N) mvalid = (neg_mask[(size_t)b * N + tid] != 0);
    unsigned bal = __ballot_sync(0xffffffffu, mvalid);
    if (lane == 0) s_wcnt[w] = __popc(bal);

    // --- load target row, compute ||t||^2 ---
    float tq = 0.0f;
    if (tid < D4) {
        float4 t = ((const float4*)(target + (size_t)b * DDIM))[tid];
        s_tgt[tid] = t;
        tq = t.x * t.x + t.y * t.y + t.z * t.z + t.w * t.w;
    }
    __syncthreads();

    int off = 0, M = 0;
#pragma unroll
    for (int j = 0; j < NWARPS; j++) {
        int c = s_wcnt[j];
        if (j < w) off += c;
        M += c;
    }
    if (mvalid) s_valid[off + __popc(bal & ((1u << lane) - 1u))] = tid;

    float tsum = blockReduceSum(tq, s_red);
    if (tid == 0) s_bcast[0] = sqrtf(tsum);
    __syncthreads();

    // --- gathered positive: dot + norm ---
    const int pi = pos_idx[b];
    const float4* pos4 = (const float4*)(positives + ((size_t)b * P + pi) * (size_t)DDIM);
    float pdot = 0.0f, pq = 0.0f;
    if (tid < D4) {
        float4 p = pos4[tid];
        float4 t = s_tgt[tid];
        pdot = fmaf(p.x, t.x, fmaf(p.y, t.y, fmaf(p.z, t.z, p.w * t.w)));
        pq   = fmaf(p.x, p.x, fmaf(p.y, p.y, fmaf(p.z, p.z, p.w * p.w)));
    }
    float pd = blockReduceSum(pdot, s_red);
    __syncthreads();
    float pn = blockReduceSum(pq, s_red);
    if (tid == 0) {
        float denom = fmaxf(sqrtf(pn) * s_bcast[0], COS_EPS);
        s_bcast[1] = (pd / denom) * TEMP_INV;
    }
    __syncthreads();
    const float tnorm = s_bcast[0];
    const float pos_sim = s_bcast[1];

    // --- valid negatives: TWO rows per warp per iter (8 LDG.128 in flight) ---
    const float4* negb = (const float4*)(negatives + (size_t)b * (size_t)N * DDIM);
    const int npairs = M >> 1;
    for (int p = w; p < npairs; p += NWARPS) {
        const float4* v0 = negb + (size_t)s_valid[2 * p] * D4;
        const float4* v1 = negb + (size_t)s_valid[2 * p + 1] * D4;
        float4 x0[4], x1[4];
#pragma unroll
        for (int k = 0; k < 4; k++) x0[k] = v0[lane + 32 * k];
#pragma unroll
        for (int k = 0; k < 4; k++) x1[k] = v1[lane + 32 * k];

        float d0 = 0.0f, q0 = 0.0f, d1 = 0.0f, q1 = 0.0f;
#pragma unroll
        for (int k = 0; k < 4; k++) {
            float4 t = s_tgt[lane + 32 * k];
            d0 = fmaf(x0[k].x, t.x, d0); d0 = fmaf(x0[k].y, t.y, d0);
            d0 = fmaf(x0[k].z, t.z, d0); d0 = fmaf(x0[k].w, t.w, d0);
            q0 = fmaf(x0[k].x, x0[k].x, q0); q0 = fmaf(x0[k].y, x0[k].y, q0);
            q0 = fmaf(x0[k].z, x0[k].z, q0); q0 = fmaf(x0[k].w, x0[k].w, q0);
            d1 = fmaf(x1[k].x, t.x, d1); d1 = fmaf(x1[k].y, t.y, d1);
            d1 = fmaf(x1[k].z, t.z, d1); d1 = fmaf(x1[k].w, t.w, d1);
            q1 = fmaf(x1[k].x, x1[k].x, q1); q1 = fmaf(x1[k].y, x1[k].y, q1);
            q1 = fmaf(x1[k].z, x1[k].z, q1); q1 = fmaf(x1[k].w, x1[k].w, q1);
        }
        // pairwise shuffle reduce both rows together
        d0 = warpReduceSum(d0); q0 = warpReduceSum(q0);
        d1 = warpReduceSum(d1); q1 = warpReduceSum(q1);
        if (lane == 0) {
            s_sims[2 * p]     = (d0 / fmaxf(sqrtf(q0) * tnorm, COS_EPS)) * TEMP_INV;
            s_sims[2 * p + 1] = (d1 / fmaxf(sqrtf(q1) * tnorm, COS_EPS)) * TEMP_INV;
        }
    }
    // odd leftover row, round-robin warp
    if ((M & 1) && w == (npairs % NWARPS)) {
        const float4* v = negb + (size_t)s_valid[M - 1] * D4;
        float dot = 0.0f, q = 0.0f;
#pragma unroll
        for (int k = 0; k < 4; k++) {
            float4 x = v[lane + 32 * k];
            float4 t = s_tgt[lane + 32 * k];
            dot = fmaf(x.x, t.x, dot); dot = fmaf(x.y, t.y, dot);
            dot = fmaf(x.z, t.z, dot); dot = fmaf(x.w, t.w, dot);
            q = fmaf(x.x, x.x, q); q = fmaf(x.y, x.y, q);
            q = fmaf(x.z, x.z, q); q = fmaf(x.w, x.w, q);
        }
        dot = warpReduceSum(dot);
        q = warpReduceSum(q);
        if (lane == 0)
            s_sims[M - 1] = (dot / fmaxf(sqrtf(q) * tnorm, COS_EPS)) * TEMP_INV;
    }
    __syncthreads();

    // --- logsumexp over [pos_sim, valid neg sims] ---
    float x = -INFINITY;
    if (tid < M) x = s_sims[tid];
    else if (tid == M) x = pos_sim;
    float m = blockReduceMax(x, s_red);
    if (tid == 0) s_bcast[2] = m;
    __syncthreads();
    m = s_bcast[2];
    float e = (x == -INFINITY) ? 0.0f : expf(x - m);
    __syncthreads();  // protect s_red reuse
    float S = blockReduceSum(e, s_red);

    // --- publish per-anchor loss; last block reduces the mean ---
    if (tid == 0) {
        g_loss[b] = logf(S) + m - pos_sim;
        __threadfence();
        unsigned int old = atomicAdd(&g_count, 1u);
        s_islast = (old == (unsigned int)(B - 1));
    }
    __syncthreads();
    if (s_islast) {
        __threadfence();
        float v = 0.0f;
        for (int i = tid; i < B; i += THREADS) v += g_loss[i];
        __syncthreads();  // s_red safe to reuse
        v = blockReduceSum(v, s_red);
        if (tid == 0) {
            out[0] = v / (float)B;
            g_count = 0;  // reset for next graph replay
        }
    }
}

extern "C" void kernel_launch(void* const* d_in, const int* in_sizes, int n_in,
                              void* d_out, int out_size) {
    const float* target = (const float*)d_in[0];
    const float* positives = (const float*)d_in[1];
    const float* negatives = (const float*)d_in[2];
    const int* pos_idx = (const int*)d_in[3];
    const int* neg_mask = (const int*)d_in[4];
    float* out = (float*)d_out;

    const int B = in_sizes[0] / DDIM;                 // 2048
    const int P = in_sizes[1] / in_sizes[0];          // 16
    const int N = in_sizes[2] / in_sizes[0];          // 128

    ntxent_main_kernel<<<B, THREADS>>>(target, positives, negatives, pos_idx,
                                       neg_mask, out, B, P, N);
}